// round 2
// baseline (speedup 1.0000x reference)
#include <cuda_runtime.h>
#include <cstddef>

// Digits_Caps dynamic routing, fused 3-pass formulation.
// B=32, C=8192, U=32, K=16, I=16, NUM_ITERS=3.
//
// u_hat[b,c,u,k] = sum_i W[c,u,k,i] * x[b,i,c]   (never materialized)
// Pass p (over all channels, u_hat recomputed in registers):
//   - compute a[c,u] from previous v (passes 2,3), update b_ij[c,u] (local per c)
//   - accumulate s~[b,u,k] += exp(b[c,u]) * u_hat[b,c,u,k],  Z[u] += exp(b[c,u])
// Small kernel between passes: s = s~/Z, squash over u -> v.

#define NBLK 152          // persistent grid (GB300 has 152 SMs)
#define NTHR 512          // one thread per (u,k) pair
#define ELEMS 16384       // B*U*K

static __device__ float g_spart[NBLK * ELEMS];   // per-CTA partial s~
static __device__ float g_zpart[NBLK * 32];      // per-CTA partial Z[u]
static __device__ float g_v[ELEMS];              // v between iterations
static __device__ float g_bij[8192 * 32];        // routing logits b[c,u]

__device__ __forceinline__ void ffma2(unsigned long long& d,
                                      const unsigned long long a,
                                      const unsigned long long b) {
  // packed f32x2 FMA (2 MACs/instr) — full-rate fp32 on sm_103a
  asm("fma.rn.f32x2 %0, %1, %2, %0;" : "+l"(d) : "l"(a), "l"(b));
}

// MODE 0: first pass (uniform weights, no a/b update, Z == C)
// MODE 1: second pass (b_old == 0, write b_ij, weights exp(b))
// MODE 2: third pass (read b_ij, weights exp(b))
template <int MODE>
__global__ __launch_bounds__(NTHR, 1) void pass_kernel(
    const float* __restrict__ x, const float* __restrict__ W) {
  extern __shared__ float smem[];
  float* x_s = smem;          // [8 channels][32 b][16 i] = 4096 floats
  float* v_s = smem + 4096;   // [b*512 + t] = 16384 floats (MODE>=1 only)

  const int t = threadIdx.x;        // t = u*16 + k
  const int u = t >> 4;
  const int k = t & 15;
  const int bid = blockIdx.x;

  if (MODE >= 1) {
#pragma unroll
    for (int r = 0; r < 32; r++) v_s[r * 512 + t] = g_v[r * 512 + t];
  }

  float acc[32];                    // s~ partial for (u,k), all 32 b
#pragma unroll
  for (int b = 0; b < 32; b++) acc[b] = 0.f;
  float accz = 0.f;

  // Current W fragment: W[c, u, k, 0:16] = 64B, as 4x LDG.128 (pairs packed for f32x2)
  ulonglong2 cw0, cw1, cw2, cw3;
  {
    const int c0 = bid * 8;
    if (c0 < 8192) {
      const ulonglong2* p = (const ulonglong2*)(W + ((size_t)c0 * 512 + t) * 16);
      cw0 = p[0]; cw1 = p[1]; cw2 = p[2]; cw3 = p[3];
    }
  }

  for (int chunk = bid; chunk < 1024; chunk += NBLK) {
    __syncthreads();
    const int cbase = chunk * 8;
    // Stage x[:, :, cbase:cbase+8] into smem (coalesced: j fastest)
#pragma unroll
    for (int r = 0; r < 8; r++) {
      const int e = t + r * 512;
      const int j = e & 7, bi = e >> 3;        // bi = b*16 + i
      x_s[j * 512 + bi] = x[(size_t)bi * 8192 + cbase + j];
    }
    __syncthreads();

#pragma unroll 1
    for (int j = 0; j < 8; j++) {
      const int c = cbase + j;

      // Prefetch next channel's W fragment (double buffer — hides DRAM latency)
      int cn = (j < 7) ? (c + 1) : (chunk + NBLK) * 8;
      ulonglong2 nw0, nw1, nw2, nw3;
      if (cn < 8192) {
        const ulonglong2* p = (const ulonglong2*)(W + ((size_t)cn * 512 + t) * 16);
        nw0 = p[0]; nw1 = p[1]; nw2 = p[2]; nw3 = p[3];
      }

      const ulonglong2* xp = (const ulonglong2*)(x_s + j * 512);
      float uh[32];
      float part = 0.f;
#pragma unroll
      for (int b = 0; b < 32; b++) {
        // uh = dot16(W[c,u,k,:], x[b,:,c]) via packed f32x2 (broadcast LDS.128)
        unsigned long long s0 = 0ull, s1 = 0ull;
        const ulonglong2 q0 = xp[b * 4 + 0];
        const ulonglong2 q1 = xp[b * 4 + 1];
        const ulonglong2 q2 = xp[b * 4 + 2];
        const ulonglong2 q3 = xp[b * 4 + 3];
        ffma2(s0, cw0.x, q0.x); ffma2(s1, cw0.y, q0.y);
        ffma2(s0, cw1.x, q1.x); ffma2(s1, cw1.y, q1.y);
        ffma2(s0, cw2.x, q2.x); ffma2(s1, cw2.y, q2.y);
        ffma2(s0, cw3.x, q3.x); ffma2(s1, cw3.y, q3.y);
        asm("add.rn.f32x2 %0, %1, %2;" : "=l"(s0) : "l"(s0), "l"(s1));
        const float lo = __uint_as_float((unsigned)s0);
        const float hi = __uint_as_float((unsigned)(s0 >> 32));
        const float val = lo + hi;
        if (MODE == 0) {
          acc[b] += val;
        } else {
          uh[b] = val;
          part = fmaf(val, v_s[b * 512 + t], part);   // a[c,u] partial
        }
      }

      if (MODE >= 1) {
        // reduce over k (16 lanes per u-group)
        part += __shfl_down_sync(0xffffffffu, part, 8, 16);
        part += __shfl_down_sync(0xffffffffu, part, 4, 16);
        part += __shfl_down_sync(0xffffffffu, part, 2, 16);
        part += __shfl_down_sync(0xffffffffu, part, 1, 16);
        float w = 0.f;
        if (k == 0) {
          const float a = part * (1.f / 32.f);   // mean over batch
          const float bnew = (MODE == 1) ? a : (g_bij[c * 32 + u] + a);
          if (MODE == 1) g_bij[c * 32 + u] = bnew;
          w = __expf(bnew);                      // unnormalized softmax weight
          accz += w;
        }
        w = __shfl_sync(0xffffffffu, w, 0, 16);
#pragma unroll
        for (int b = 0; b < 32; b++) acc[b] = fmaf(w, uh[b], acc[b]);
      }

      cw0 = nw0; cw1 = nw1; cw2 = nw2; cw3 = nw3;
    }
  }

  // Deterministic per-CTA partials (no float atomics). idx = (b*32+u)*16+k = b*512+t
#pragma unroll
  for (int b = 0; b < 32; b++)
    g_spart[(size_t)bid * ELEMS + b * 512 + t] = acc[b];
  if (MODE >= 1 && k == 0) g_zpart[bid * 32 + u] = accz;
}

// Reduce partials, normalize by Z, squash over u -> v (or final output).
// One warp per (b,k) pair; lane = u.
template <int ZMODE, bool FINAL>
__global__ void squash_kernel(float* __restrict__ out) {
  const int gw = blockIdx.x * (blockDim.x >> 5) + (threadIdx.x >> 5);
  const int lane = threadIdx.x & 31;   // = u
  if (gw >= 512) return;
  const int b = gw >> 4, k = gw & 15;
  const int idx = (b * 32 + lane) * 16 + k;

  float s = 0.f;
  for (int p = 0; p < NBLK; p++) s += g_spart[(size_t)p * ELEMS + idx];

  float Z;
  if (ZMODE == 1) {
    Z = 8192.f;   // exp(0) summed over C channels
  } else {
    Z = 0.f;
    for (int p = 0; p < NBLK; p++) Z += g_zpart[p * 32 + lane];
  }
  s /= Z;

  float msq = s * s;                       // sum over u (the 32 lanes)
#pragma unroll
  for (int o = 16; o > 0; o >>= 1) msq += __shfl_xor_sync(0xffffffffu, msq, o);

  const float v = (msq / (1.f + msq)) * s * rsqrtf(msq);
  if (FINAL) out[idx] = v;
  else       g_v[idx] = v;
}

extern "C" void kernel_launch(void* const* d_in, const int* in_sizes, int n_in,
                              void* d_out, int out_size) {
  const float* x = (const float*)d_in[0];   // (32,16,8192)  = 4,194,304
  const float* W = (const float*)d_in[1];   // (8192,32,16,16) = 67,108,864
  if (n_in >= 2 && in_sizes[0] > in_sizes[1]) {   // defensive: order by size
    const float* tmp = x; x = W; W = tmp;
  }
  float* out = (float*)d_out;

  const int SM_SMALL = 4096 * 4;            // x tile only
  const int SM_BIG = (4096 + 16384) * 4;    // x tile + v table (80 KB)
  cudaFuncSetAttribute(pass_kernel<0>, cudaFuncAttributeMaxDynamicSharedMemorySize, SM_BIG);
  cudaFuncSetAttribute(pass_kernel<1>, cudaFuncAttributeMaxDynamicSharedMemorySize, SM_BIG);
  cudaFuncSetAttribute(pass_kernel<2>, cudaFuncAttributeMaxDynamicSharedMemorySize, SM_BIG);

  // iter 1: uniform weights -> s1 -> v1
  pass_kernel<0><<<NBLK, NTHR, SM_SMALL>>>(x, W);
  squash_kernel<1, false><<<16, 1024>>>(nullptr);
  // iter 2: a1 (from v1), b1 = a1, weights exp(b1) -> s2 -> v2
  pass_kernel<1><<<NBLK, NTHR, SM_BIG>>>(x, W);
  squash_kernel<2, false><<<16, 1024>>>(nullptr);
  // iter 3: a2 (from v2), b2 = b1 + a2, weights exp(b2) -> s3 -> v3 (output)
  pass_kernel<2><<<NBLK, NTHR, SM_BIG>>>(x, W);
  squash_kernel<2, true><<<16, 1024>>>(out);
}

// round 4
// speedup vs baseline: 1.1922x; 1.1922x over previous
#include <cuda_runtime.h>
#include <cstddef>

// Digits_Caps dynamic routing. B=32, C=8192, U=32, K=16, I=16, 3 iters.
//
// New structure:
//  pass1: compute u_hat (fp32), store to 512MB scratch, accumulate s~ for iter1
//  pass23: stream u_hat back (no W, no GEMM), compute a / b update / weighted s~
//  reduce: coalesced partial reduction (fixes 48us squash)
//  squash: tiny normalize+squash

#define NBLK 152
#define NTHR 512
#define ELEMS 16384   // B*U*K
typedef unsigned long long ull;

static __device__ float g_uhat[(size_t)8192 * 512 * 32];  // [c][t=(u,k)][b] 512MB
static __device__ float g_spart[NBLK * ELEMS];
static __device__ float g_zpart[NBLK * 32];
static __device__ float g_sred[ELEMS];
static __device__ float g_zred[32];
static __device__ float g_v[ELEMS];
static __device__ float g_bij[8192 * 32];

__device__ __forceinline__ void ffma2(ull& d, const ull a, const ull b) {
  asm("fma.rn.f32x2 %0, %1, %2, %0;" : "+l"(d) : "l"(a), "l"(b));
}
__device__ __forceinline__ void add2(ull& d, const ull a) {
  asm("add.rn.f32x2 %0, %0, %1;" : "+l"(d) : "l"(a));
}
__device__ __forceinline__ ull dup2(float a) {
  unsigned u = __float_as_uint(a);
  return ((ull)u << 32) | u;
}
__device__ __forceinline__ float lo2(ull a) { return __uint_as_float((unsigned)a); }
__device__ __forceinline__ float hi2(ull a) { return __uint_as_float((unsigned)(a >> 32)); }

// x_s layout: [j][i][b] with i-stride 36 (bank spread + 16B alignment)
#define XS_J 576   // 16*36
#define XS_I 36

// ---------------- pass 1: GEMM + store u_hat + s~ (uniform weights) -------
__global__ __launch_bounds__(NTHR, 1) void pass1_kernel(
    const float* __restrict__ x, const float* __restrict__ W) {
  __shared__ float x_s[8 * XS_J];
  const int t = threadIdx.x;
  const int bid = blockIdx.x;

  ull acc2[16];
#pragma unroll
  for (int p = 0; p < 16; p++) acc2[p] = 0ull;

  float cwf[16];
  {
    const float4* wp = (const float4*)(W + ((size_t)(bid * 8) * 512 + t) * 16);
    float4 a0 = wp[0], a1 = wp[1], a2 = wp[2], a3 = wp[3];
    cwf[0]=a0.x; cwf[1]=a0.y; cwf[2]=a0.z; cwf[3]=a0.w;
    cwf[4]=a1.x; cwf[5]=a1.y; cwf[6]=a1.z; cwf[7]=a1.w;
    cwf[8]=a2.x; cwf[9]=a2.y; cwf[10]=a2.z; cwf[11]=a2.w;
    cwf[12]=a3.x; cwf[13]=a3.y; cwf[14]=a3.z; cwf[15]=a3.w;
  }

  for (int chunk = bid; chunk < 1024; chunk += NBLK) {
    __syncthreads();
    const int cbase = chunk * 8;
#pragma unroll
    for (int r = 0; r < 8; r++) {
      const int e = t + r * 512;
      const int j = e & 7, bi = e >> 3;
      const int i = bi & 15, b = bi >> 4;
      x_s[j * XS_J + i * XS_I + b] = x[(size_t)bi * 8192 + cbase + j];
    }
    __syncthreads();

#pragma unroll 1
    for (int j = 0; j < 8; j++) {
      const int c = cbase + j;

      // prefetch next channel's W
      const int cn = (j < 7) ? (c + 1) : (chunk + NBLK) * 8;
      float nwf[16];
      if (cn < 8192) {
        const float4* wp = (const float4*)(W + ((size_t)cn * 512 + t) * 16);
        float4 a0 = wp[0], a1 = wp[1], a2 = wp[2], a3 = wp[3];
        nwf[0]=a0.x; nwf[1]=a0.y; nwf[2]=a0.z; nwf[3]=a0.w;
        nwf[4]=a1.x; nwf[5]=a1.y; nwf[6]=a1.z; nwf[7]=a1.w;
        nwf[8]=a2.x; nwf[9]=a2.y; nwf[10]=a2.z; nwf[11]=a2.w;
        nwf[12]=a3.x; nwf[13]=a3.y; nwf[14]=a3.z; nwf[15]=a3.w;
      }

      ull uh2[16];
#pragma unroll
      for (int p = 0; p < 16; p++) uh2[p] = 0ull;

#pragma unroll
      for (int i = 0; i < 16; i++) {
        const ull wd = dup2(cwf[i]);
        const ulonglong2* xp = (const ulonglong2*)(x_s + j * XS_J + i * XS_I);
#pragma unroll
        for (int q = 0; q < 8; q++) {
          const ulonglong2 xv = xp[q];
          ffma2(uh2[2 * q],     wd, xv.x);
          ffma2(uh2[2 * q + 1], wd, xv.y);
        }
      }

      // store u_hat (fp32, b contiguous) + accumulate s~ (w = 1)
      ulonglong2* up = (ulonglong2*)(g_uhat + ((size_t)c * 512 + t) * 32);
#pragma unroll
      for (int p = 0; p < 8; p++) {
        ulonglong2 o; o.x = uh2[2 * p]; o.y = uh2[2 * p + 1];
        up[p] = o;
      }
#pragma unroll
      for (int p = 0; p < 16; p++) add2(acc2[p], uh2[p]);

#pragma unroll
      for (int p = 0; p < 16; p++) cwf[p] = nwf[p];
    }
  }

#pragma unroll
  for (int p = 0; p < 16; p++) {
    g_spart[(size_t)bid * ELEMS + (2 * p)     * 512 + t] = lo2(acc2[p]);
    g_spart[(size_t)bid * ELEMS + (2 * p + 1) * 512 + t] = hi2(acc2[p]);
  }
}

// ---------------- passes 2/3: stream u_hat, routing update ----------------
// MODE 1: b_old == 0, write b_ij.  MODE 2: read b_ij (final, no write).
template <int MODE>
__global__ __launch_bounds__(NTHR, 1) void pass23_kernel() {
  extern __shared__ float v_s[];   // [t][b] stride 34 -> 69632 B
  const int t = threadIdx.x;
  const int u = t >> 4;
  const int k = t & 15;
  const int bid = blockIdx.x;

#pragma unroll
  for (int b = 0; b < 32; b++) v_s[t * 34 + b] = g_v[b * 512 + t];
  __syncthreads();

  ull acc2[16];
#pragma unroll
  for (int p = 0; p < 16; p++) acc2[p] = 0ull;
  float accz = 0.f;

  ulonglong2 cb[8];
  {
    const ulonglong2* up = (const ulonglong2*)(g_uhat + ((size_t)bid * 512 + t) * 32);
#pragma unroll
    for (int p = 0; p < 8; p++) cb[p] = up[p];
  }

#pragma unroll 1
  for (int c = bid; c < 8192; c += NBLK) {
    const int cn = c + NBLK;
    ulonglong2 nb[8];
    if (cn < 8192) {
      const ulonglong2* up = (const ulonglong2*)(g_uhat + ((size_t)cn * 512 + t) * 32);
#pragma unroll
      for (int p = 0; p < 8; p++) nb[p] = up[p];
    }

    // a[c,u] partial: dot over b of uh * v (b-packed)
    ull part2 = 0ull;
#pragma unroll
    for (int p = 0; p < 8; p++) {
      const ull v0 = *(const ull*)(v_s + t * 34 + 4 * p);
      const ull v1 = *(const ull*)(v_s + t * 34 + 4 * p + 2);
      ffma2(part2, cb[p].x, v0);
      ffma2(part2, cb[p].y, v1);
    }
    float part = lo2(part2) + hi2(part2);
    part += __shfl_down_sync(0xffffffffu, part, 8, 16);
    part += __shfl_down_sync(0xffffffffu, part, 4, 16);
    part += __shfl_down_sync(0xffffffffu, part, 2, 16);
    part += __shfl_down_sync(0xffffffffu, part, 1, 16);

    float w = 0.f;
    if (k == 0) {
      const float a = part * (1.f / 32.f);
      const float bnew = (MODE == 1) ? a : (g_bij[c * 32 + u] + a);
      if (MODE == 1) g_bij[c * 32 + u] = bnew;
      w = __expf(bnew);
      accz += w;
    }
    w = __shfl_sync(0xffffffffu, w, 0, 16);
    const ull wd = dup2(w);
#pragma unroll
    for (int p = 0; p < 8; p++) {
      ffma2(acc2[2 * p],     wd, cb[p].x);
      ffma2(acc2[2 * p + 1], wd, cb[p].y);
    }

#pragma unroll
    for (int p = 0; p < 8; p++) cb[p] = nb[p];
  }

#pragma unroll
  for (int p = 0; p < 16; p++) {
    g_spart[(size_t)bid * ELEMS + (2 * p)     * 512 + t] = lo2(acc2[p]);
    g_spart[(size_t)bid * ELEMS + (2 * p + 1) * 512 + t] = hi2(acc2[p]);
  }
  if (k == 0) g_zpart[bid * 32 + u] = accz;
}

// ---------------- coalesced partial reduction -----------------------------
template <bool WITH_Z>
__global__ void reduce_kernel() {
  const int idx = blockIdx.x * 512 + threadIdx.x;   // grid 32 x 512
  float s = 0.f;
#pragma unroll 8
  for (int p = 0; p < NBLK; p++) s += g_spart[(size_t)p * ELEMS + idx];
  g_sred[idx] = s;
  if (WITH_Z && blockIdx.x == 0 && threadIdx.x < 32) {
    float z = 0.f;
#pragma unroll 8
    for (int p = 0; p < NBLK; p++) z += g_zpart[p * 32 + threadIdx.x];
    g_zred[threadIdx.x] = z;
  }
}

// ---------------- squash --------------------------------------------------
template <int ZMODE, bool FINAL>
__global__ void squash_kernel(float* __restrict__ out) {
  const int gw = blockIdx.x * (blockDim.x >> 5) + (threadIdx.x >> 5);
  const int lane = threadIdx.x & 31;   // = u
  if (gw >= 512) return;
  const int b = gw >> 4, k = gw & 15;
  const int idx = (b * 32 + lane) * 16 + k;

  float s = g_sred[idx];
  const float Z = (ZMODE == 1) ? 8192.f : g_zred[lane];
  s /= Z;

  float msq = s * s;
#pragma unroll
  for (int o = 16; o > 0; o >>= 1) msq += __shfl_xor_sync(0xffffffffu, msq, o);

  const float v = (msq / (1.f + msq)) * s * rsqrtf(msq);
  if (FINAL) out[idx] = v;
  else       g_v[idx] = v;
}

extern "C" void kernel_launch(void* const* d_in, const int* in_sizes, int n_in,
                              void* d_out, int out_size) {
  const float* x = (const float*)d_in[0];   // (32,16,8192)
  const float* W = (const float*)d_in[1];   // (8192,32,16,16)
  if (n_in >= 2 && in_sizes[0] > in_sizes[1]) {
    const float* tmp = x; x = W; W = tmp;
  }
  float* out = (float*)d_out;

  const int SM_V = 512 * 34 * 4;   // 69632 B
  cudaFuncSetAttribute(pass23_kernel<1>, cudaFuncAttributeMaxDynamicSharedMemorySize, SM_V);
  cudaFuncSetAttribute(pass23_kernel<2>, cudaFuncAttributeMaxDynamicSharedMemorySize, SM_V);

  // iter 1: u_hat + uniform s~ -> v1
  pass1_kernel<<<NBLK, NTHR>>>(x, W);
  reduce_kernel<false><<<32, 512>>>();
  squash_kernel<1, false><<<16, 1024>>>(nullptr);
  // iter 2
  pass23_kernel<1><<<NBLK, NTHR, SM_V>>>();
  reduce_kernel<true><<<32, 512>>>();
  squash_kernel<2, false><<<16, 1024>>>(nullptr);
  // iter 3
  pass23_kernel<2><<<NBLK, NTHR, SM_V>>>();
  reduce_kernel<true><<<32, 512>>>();
  squash_kernel<2, true><<<16, 1024>>>(out);
}

// round 5
// speedup vs baseline: 2.0640x; 1.7312x over previous
#include <cuda_runtime.h>
#include <cuda_fp16.h>
#include <cstddef>

// Digits_Caps dynamic routing. B=32, C=8192, U=32, K=16, I=16, 3 iters.
// pass1: fp32 GEMM for u_hat, store fp16 COALESCED, accumulate s~ (iter1)
// pass23: stream fp16 u_hat (coalesced), routing update, weighted s~
// reduce: coalesced partial reduction; squash: tiny normalize+squash

#define NBLK 152
#define NTHR 512
#define ELEMS 16384   // B*U*K
typedef unsigned long long ull;

// fp16 u_hat, layout [c][qq=0..3][t=0..511][8 halfs (b=8qq..8qq+7)] = 256 MB
static __device__ uint4 g_uhat[(size_t)8192 * 4 * 512];
static __device__ float g_spart[NBLK * ELEMS];
static __device__ float g_zpart[NBLK * 32];
static __device__ float g_sred[ELEMS];
static __device__ float g_zred[32];
static __device__ float g_v[ELEMS];
static __device__ float g_bij[8192 * 32];

__device__ __forceinline__ void ffma2(ull& d, const ull a, const ull b) {
  asm("fma.rn.f32x2 %0, %1, %2, %0;" : "+l"(d) : "l"(a), "l"(b));
}
__device__ __forceinline__ void add2(ull& d, const ull a) {
  asm("add.rn.f32x2 %0, %0, %1;" : "+l"(d) : "l"(a));
}
__device__ __forceinline__ ull dup2(float a) {
  unsigned u = __float_as_uint(a);
  return ((ull)u << 32) | u;
}
__device__ __forceinline__ float lo2(ull a) { return __uint_as_float((unsigned)a); }
__device__ __forceinline__ float hi2(ull a) { return __uint_as_float((unsigned)(a >> 32)); }

// packed fp32 pair (lo=b_even, hi=b_odd) -> half2 {lo, hi}
__device__ __forceinline__ unsigned f2h2(ull a) {
  unsigned r;
  asm("cvt.rn.f16x2.f32 %0, %1, %2;" : "=r"(r)
      : "r"((unsigned)(a >> 32)), "r"((unsigned)a));
  return r;
}
__device__ __forceinline__ float2 h2f2(unsigned v) {
  __half2 h = *reinterpret_cast<__half2*>(&v);
  return __half22float2(h);
}

// x_s layout: [j][i][b] i-stride 36 (bank spread, 16B aligned)
#define XS_J 576
#define XS_I 36

// ---------------- pass 1: GEMM + coalesced fp16 u_hat store + s~ ----------
__global__ __launch_bounds__(NTHR, 1) void pass1_kernel(
    const float* __restrict__ x, const float* __restrict__ W) {
  __shared__ float x_s[8 * XS_J];
  const int t = threadIdx.x;
  const int bid = blockIdx.x;

  ull acc2[16];
#pragma unroll
  for (int p = 0; p < 16; p++) acc2[p] = 0ull;

  float cwf[16];
  {
    const float4* wp = (const float4*)(W + ((size_t)(bid * 8) * 512 + t) * 16);
    float4 a0 = wp[0], a1 = wp[1], a2 = wp[2], a3 = wp[3];
    cwf[0]=a0.x; cwf[1]=a0.y; cwf[2]=a0.z; cwf[3]=a0.w;
    cwf[4]=a1.x; cwf[5]=a1.y; cwf[6]=a1.z; cwf[7]=a1.w;
    cwf[8]=a2.x; cwf[9]=a2.y; cwf[10]=a2.z; cwf[11]=a2.w;
    cwf[12]=a3.x; cwf[13]=a3.y; cwf[14]=a3.z; cwf[15]=a3.w;
  }

  for (int chunk = bid; chunk < 1024; chunk += NBLK) {
    __syncthreads();
    const int cbase = chunk * 8;
#pragma unroll
    for (int r = 0; r < 8; r++) {
      const int e = t + r * 512;
      const int j = e & 7, bi = e >> 3;
      const int i = bi & 15, b = bi >> 4;
      x_s[j * XS_J + i * XS_I + b] = x[(size_t)bi * 8192 + cbase + j];
    }
    __syncthreads();

#pragma unroll 1
    for (int j = 0; j < 8; j++) {
      const int c = cbase + j;

      const int cn = (j < 7) ? (c + 1) : (chunk + NBLK) * 8;
      float nwf[16];
      if (cn < 8192) {
        const float4* wp = (const float4*)(W + ((size_t)cn * 512 + t) * 16);
        float4 a0 = wp[0], a1 = wp[1], a2 = wp[2], a3 = wp[3];
        nwf[0]=a0.x; nwf[1]=a0.y; nwf[2]=a0.z; nwf[3]=a0.w;
        nwf[4]=a1.x; nwf[5]=a1.y; nwf[6]=a1.z; nwf[7]=a1.w;
        nwf[8]=a2.x; nwf[9]=a2.y; nwf[10]=a2.z; nwf[11]=a2.w;
        nwf[12]=a3.x; nwf[13]=a3.y; nwf[14]=a3.z; nwf[15]=a3.w;
      }

      ull uh2[16];
#pragma unroll
      for (int p = 0; p < 16; p++) uh2[p] = 0ull;

#pragma unroll
      for (int i = 0; i < 16; i++) {
        const ull wd = dup2(cwf[i]);
        const ulonglong2* xp = (const ulonglong2*)(x_s + j * XS_J + i * XS_I);
#pragma unroll
        for (int q = 0; q < 8; q++) {
          const ulonglong2 xv = xp[q];
          ffma2(uh2[2 * q],     wd, xv.x);
          ffma2(uh2[2 * q + 1], wd, xv.y);
        }
      }

      // coalesced fp16 store: [c][qq][t]{8 halfs}
      uint4* up = g_uhat + (size_t)c * 2048 + t;
#pragma unroll
      for (int qq = 0; qq < 4; qq++) {
        uint4 o;
        o.x = f2h2(uh2[4 * qq + 0]);
        o.y = f2h2(uh2[4 * qq + 1]);
        o.z = f2h2(uh2[4 * qq + 2]);
        o.w = f2h2(uh2[4 * qq + 3]);
        up[qq * 512] = o;
      }
#pragma unroll
      for (int p = 0; p < 16; p++) add2(acc2[p], uh2[p]);

#pragma unroll
      for (int p = 0; p < 16; p++) cwf[p] = nwf[p];
    }
  }

#pragma unroll
  for (int p = 0; p < 16; p++) {
    g_spart[(size_t)bid * ELEMS + (2 * p)     * 512 + t] = lo2(acc2[p]);
    g_spart[(size_t)bid * ELEMS + (2 * p + 1) * 512 + t] = hi2(acc2[p]);
  }
}

// ---------------- passes 2/3: stream fp16 u_hat, routing update -----------
// MODE 1: b_old == 0, write b_ij.  MODE 2: read b_ij (final).
template <int MODE>
__global__ __launch_bounds__(NTHR, 1) void pass23_kernel() {
  extern __shared__ float v_s[];   // [t][b] stride 33: conflict-free scalar LDS
  const int t = threadIdx.x;
  const int u = t >> 4;
  const int k = t & 15;
  const int bid = blockIdx.x;

#pragma unroll
  for (int b = 0; b < 32; b++) v_s[t * 33 + b] = g_v[b * 512 + t];
  __syncthreads();

  float acc[32];
#pragma unroll
  for (int b = 0; b < 32; b++) acc[b] = 0.f;
  float accz = 0.f;

  uint4 cur[4];
  {
    const uint4* up = g_uhat + (size_t)bid * 2048 + t;
#pragma unroll
    for (int qq = 0; qq < 4; qq++) cur[qq] = up[qq * 512];
  }

#pragma unroll 1
  for (int c = bid; c < 8192; c += NBLK) {
    const int cn = c + NBLK;
    uint4 nxt[4];
    if (cn < 8192) {
      const uint4* up = g_uhat + (size_t)cn * 2048 + t;
#pragma unroll
      for (int qq = 0; qq < 4; qq++) nxt[qq] = up[qq * 512];
    }

    // a[c,u] partial: dot over b of uh * v
    float part = 0.f;
#pragma unroll
    for (int qq = 0; qq < 4; qq++) {
      const unsigned hw[4] = {cur[qq].x, cur[qq].y, cur[qq].z, cur[qq].w};
#pragma unroll
      for (int w = 0; w < 4; w++) {
        const float2 f = h2f2(hw[w]);
        const int b0 = qq * 8 + w * 2;
        part = fmaf(f.x, v_s[t * 33 + b0],     part);
        part = fmaf(f.y, v_s[t * 33 + b0 + 1], part);
      }
    }
    part += __shfl_down_sync(0xffffffffu, part, 8, 16);
    part += __shfl_down_sync(0xffffffffu, part, 4, 16);
    part += __shfl_down_sync(0xffffffffu, part, 2, 16);
    part += __shfl_down_sync(0xffffffffu, part, 1, 16);

    float wt = 0.f;
    if (k == 0) {
      const float a = part * (1.f / 32.f);
      const float bnew = (MODE == 1) ? a : (g_bij[c * 32 + u] + a);
      if (MODE == 1) g_bij[c * 32 + u] = bnew;
      wt = __expf(bnew);
      accz += wt;
    }
    wt = __shfl_sync(0xffffffffu, wt, 0, 16);

#pragma unroll
    for (int qq = 0; qq < 4; qq++) {
      const unsigned hw[4] = {cur[qq].x, cur[qq].y, cur[qq].z, cur[qq].w};
#pragma unroll
      for (int w = 0; w < 4; w++) {
        const float2 f = h2f2(hw[w]);
        const int b0 = qq * 8 + w * 2;
        acc[b0]     = fmaf(wt, f.x, acc[b0]);
        acc[b0 + 1] = fmaf(wt, f.y, acc[b0 + 1]);
      }
    }

#pragma unroll
    for (int qq = 0; qq < 4; qq++) cur[qq] = nxt[qq];
  }

#pragma unroll
  for (int b = 0; b < 32; b++)
    g_spart[(size_t)bid * ELEMS + b * 512 + t] = acc[b];
  if (k == 0) g_zpart[bid * 32 + u] = accz;
}

// ---------------- coalesced partial reduction -----------------------------
template <bool WITH_Z>
__global__ void reduce_kernel() {
  const int idx = blockIdx.x * 512 + threadIdx.x;   // grid 32 x 512
  float s = 0.f;
#pragma unroll 8
  for (int p = 0; p < NBLK; p++) s += g_spart[(size_t)p * ELEMS + idx];
  g_sred[idx] = s;
  if (WITH_Z && blockIdx.x == 0 && threadIdx.x < 32) {
    float z = 0.f;
#pragma unroll 8
    for (int p = 0; p < NBLK; p++) z += g_zpart[p * 32 + threadIdx.x];
    g_zred[threadIdx.x] = z;
  }
}

// ---------------- squash --------------------------------------------------
template <int ZMODE, bool FINAL>
__global__ void squash_kernel(float* __restrict__ out) {
  const int gw = blockIdx.x * (blockDim.x >> 5) + (threadIdx.x >> 5);
  const int lane = threadIdx.x & 31;   // = u
  if (gw >= 512) return;
  const int b = gw >> 4, k = gw & 15;
  const int idx = (b * 32 + lane) * 16 + k;

  float s = g_sred[idx];
  const float Z = (ZMODE == 1) ? 8192.f : g_zred[lane];
  s /= Z;

  float msq = s * s;
#pragma unroll
  for (int o = 16; o > 0; o >>= 1) msq += __shfl_xor_sync(0xffffffffu, msq, o);

  const float v = (msq / (1.f + msq)) * s * rsqrtf(msq);
  if (FINAL) out[idx] = v;
  else       g_v[idx] = v;
}

extern "C" void kernel_launch(void* const* d_in, const int* in_sizes, int n_in,
                              void* d_out, int out_size) {
  const float* x = (const float*)d_in[0];   // (32,16,8192)
  const float* W = (const float*)d_in[1];   // (8192,32,16,16)
  if (n_in >= 2 && in_sizes[0] > in_sizes[1]) {
    const float* tmp = x; x = W; W = tmp;
  }
  float* out = (float*)d_out;

  const int SM_V = 512 * 33 * 4;   // 67584 B
  cudaFuncSetAttribute(pass23_kernel<1>, cudaFuncAttributeMaxDynamicSharedMemorySize, SM_V);
  cudaFuncSetAttribute(pass23_kernel<2>, cudaFuncAttributeMaxDynamicSharedMemorySize, SM_V);

  // iter 1
  pass1_kernel<<<NBLK, NTHR>>>(x, W);
  reduce_kernel<false><<<32, 512>>>();
  squash_kernel<1, false><<<16, 1024>>>(nullptr);
  // iter 2
  pass23_kernel<1><<<NBLK, NTHR, SM_V>>>();
  reduce_kernel<true><<<32, 512>>>();
  squash_kernel<2, false><<<16, 1024>>>(nullptr);
  // iter 3
  pass23_kernel<2><<<NBLK, NTHR, SM_V>>>();
  reduce_kernel<true><<<32, 512>>>();
  squash_kernel<2, true><<<16, 1024>>>(out);
}

// round 6
// speedup vs baseline: 2.3880x; 1.1570x over previous
#include <cuda_runtime.h>
#include <cuda_fp16.h>
#include <cstddef>

// Digits_Caps dynamic routing. B=32, C=8192, U=32, K=16, I=16, 3 iters.
// pass1: fp32 GEMM u_hat (2t x 16b per thread), store fp16 coalesced, s~ in smem
// pass23: stream fp16 u_hat (2 CTAs/SM), routing update, weighted s~
// reduce: parallel partial reduction; squash: tiny normalize+squash

#define NSTRIPE 152
#define ELEMS 16384   // B*U*K
typedef unsigned long long ull;

// fp16 u_hat: [c][qq=0..3][t=0..511][8 halfs b=8qq..8qq+7] = 256 MB
static __device__ uint4 g_uhat[(size_t)8192 * 4 * 512];
static __device__ float g_spart[NSTRIPE * ELEMS];
static __device__ float g_zpart[NSTRIPE * 32];
static __device__ float g_sred[ELEMS];
static __device__ float g_zred[32];
static __device__ float g_v[ELEMS];
static __device__ float g_bij[8192 * 32];

__device__ __forceinline__ void ffma2(ull& d, const ull a, const ull b) {
  asm("fma.rn.f32x2 %0, %1, %2, %0;" : "+l"(d) : "l"(a), "l"(b));
}
__device__ __forceinline__ void add2(ull& d, const ull a) {
  asm("add.rn.f32x2 %0, %0, %1;" : "+l"(d) : "l"(a));
}
__device__ __forceinline__ ull dup2(float a) {
  unsigned u = __float_as_uint(a);
  return ((ull)u << 32) | u;
}
__device__ __forceinline__ float lo2(ull a) { return __uint_as_float((unsigned)a); }
__device__ __forceinline__ float hi2(ull a) { return __uint_as_float((unsigned)(a >> 32)); }
__device__ __forceinline__ unsigned f2h2(ull a) {   // {lo->low half, hi->high half}
  unsigned r;
  asm("cvt.rn.f16x2.f32 %0, %1, %2;" : "=r"(r)
      : "r"((unsigned)(a >> 32)), "r"((unsigned)a));
  return r;
}
__device__ __forceinline__ float2 h2f2(unsigned v) {
  __half2 h = *reinterpret_cast<__half2*>(&v);
  return __half22float2(h);
}
__device__ __forceinline__ void pref_l2(const void* p) {
  asm volatile("prefetch.global.L2 [%0];" :: "l"(p));
}

// x_s layout: [j][i][b], i-stride 36 floats (16B aligned), j-stride 584 (bank-spread)
#define XS_J 584
#define XS_I 36
#define XS_BYTES (8 * XS_J * 4)   // 18688

// ---------------- pass 1: GEMM + fp16 u_hat store + s~ (smem acc) ---------
__global__ __launch_bounds__(512, 1) void pass1_kernel(
    const float* __restrict__ x, const float* __restrict__ W) {
  extern __shared__ char smem_raw[];
  float* x_s = (float*)smem_raw;
  ull* sacc = (ull*)(smem_raw + XS_BYTES);   // [16 p][512 t] = 64 KB

  const int t = threadIdx.x;
  const int tl = t & 255;          // base t (also t+256)
  const int bh = t >> 8;           // batch half: b in [bh*16, bh*16+16)
  const int bid = blockIdx.x;

#pragma unroll
  for (int p = 0; p < 16; p++) sacc[p * 512 + t] = 0ull;

  for (int chunk = bid; chunk < 1024; chunk += NSTRIPE) {
    __syncthreads();
    const int cbase = chunk * 8;
#pragma unroll
    for (int r = 0; r < 8; r++) {
      const int e = t + r * 512;
      const int j = e & 7, bi = e >> 3;
      const int i = bi & 15, b = bi >> 4;
      x_s[j * XS_J + i * XS_I + b] = x[(size_t)bi * 8192 + cbase + j];
    }
    __syncthreads();

#pragma unroll 1
    for (int j = 0; j < 8; j++) {
      const int c = cbase + j;

      // W for the thread's two t values (16 floats each)
      float cwa[16], cwb[16];
      {
        const float4* wa = (const float4*)(W + ((size_t)c * 512 + tl) * 16);
        const float4* wb = (const float4*)(W + ((size_t)c * 512 + tl + 256) * 16);
#pragma unroll
        for (int q = 0; q < 4; q++) {
          float4 va = wa[q], vb = wb[q];
          cwa[4*q]=va.x; cwa[4*q+1]=va.y; cwa[4*q+2]=va.z; cwa[4*q+3]=va.w;
          cwb[4*q]=vb.x; cwb[4*q+1]=vb.y; cwb[4*q+2]=vb.z; cwb[4*q+3]=vb.w;
        }
      }
      // register-free prefetch of next channel's W into L2
      {
        const int cn = (j < 7) ? (c + 1) : (chunk + NSTRIPE) * 8;
        if (cn < 8192) {
          pref_l2(W + ((size_t)cn * 512 + tl) * 16);
          pref_l2(W + ((size_t)cn * 512 + tl + 256) * 16);
        }
      }

      ull uh2[16];   // [tp*8 + bp]: pair b = bh*16 + 2*bp (+1)
#pragma unroll
      for (int p = 0; p < 16; p++) uh2[p] = 0ull;

#pragma unroll
      for (int i = 0; i < 16; i++) {
        const ull wA = dup2(cwa[i]);
        const ull wB = dup2(cwb[i]);
        const ulonglong2* xp =
            (const ulonglong2*)(x_s + j * XS_J + i * XS_I + bh * 16);
#pragma unroll
        for (int q = 0; q < 4; q++) {
          const ulonglong2 xv = xp[q];   // broadcast LDS.128, reused by 4 FFMA2
          ffma2(uh2[2*q],       wA, xv.x);
          ffma2(uh2[2*q + 1],   wA, xv.y);
          ffma2(uh2[8 + 2*q],   wB, xv.x);
          ffma2(uh2[8 + 2*q+1], wB, xv.y);
        }
      }

      // fp16 store, fully coalesced: [c][qq][t]{8 halfs}, qq = 2*bh + qh
#pragma unroll
      for (int tp = 0; tp < 2; tp++) {
#pragma unroll
        for (int qh = 0; qh < 2; qh++) {
          uint4 o;
          o.x = f2h2(uh2[tp*8 + qh*4 + 0]);
          o.y = f2h2(uh2[tp*8 + qh*4 + 1]);
          o.z = f2h2(uh2[tp*8 + qh*4 + 2]);
          o.w = f2h2(uh2[tp*8 + qh*4 + 3]);
          g_uhat[(size_t)c * 2048 + (2*bh + qh) * 512 + tl + tp * 256] = o;
        }
      }
      // s~ accumulate in smem (frees 32 registers)
#pragma unroll
      for (int p = 0; p < 16; p++) {
        ull v = sacc[p * 512 + t];
        add2(v, uh2[p]);
        sacc[p * 512 + t] = v;
      }
    }
  }

#pragma unroll
  for (int p = 0; p < 16; p++) {
    const ull v = sacc[p * 512 + t];
    const int b0 = bh * 16 + 2 * (p & 7);
    const int tg = tl + (p >> 3) * 256;
    g_spart[(size_t)bid * ELEMS + b0 * 512 + tg]       = lo2(v);
    g_spart[(size_t)bid * ELEMS + (b0 + 1) * 512 + tg] = hi2(v);
  }
}

// ---------------- passes 2/3: stream fp16 u_hat, routing update -----------
// MODE 1: b_old == 0, write b_ij.  MODE 2: read b_ij (final).
template <int MODE>
__global__ __launch_bounds__(256, 2) void pass23_kernel() {
  extern __shared__ float v_s[];   // [tid][b] stride 33
  const int tid = threadIdx.x;
  const int half = blockIdx.x & 1;
  const int stripe = blockIdx.x >> 1;
  const int tg = half * 256 + tid;
  const int u = tg >> 4;
  const int k = tg & 15;

#pragma unroll
  for (int b = 0; b < 32; b++) v_s[tid * 33 + b] = g_v[b * 512 + tg];
  __syncthreads();

  float acc[32];
#pragma unroll
  for (int b = 0; b < 32; b++) acc[b] = 0.f;
  float accz = 0.f;

  uint4 cur[4];
  {
    const uint4* up = g_uhat + (size_t)stripe * 2048 + tg;
#pragma unroll
    for (int qq = 0; qq < 4; qq++) cur[qq] = up[qq * 512];
  }

#pragma unroll 1
  for (int c = stripe; c < 8192; c += NSTRIPE) {
    const int cn = c + NSTRIPE;
    uint4 nxt[4];
    if (cn < 8192) {
      const uint4* up = g_uhat + (size_t)cn * 2048 + tg;
#pragma unroll
      for (int qq = 0; qq < 4; qq++) nxt[qq] = up[qq * 512];
      if (cn + NSTRIPE < 8192) {
        const uint4* pp = g_uhat + (size_t)(cn + NSTRIPE) * 2048 + tg;
#pragma unroll
        for (int qq = 0; qq < 4; qq++) pref_l2(pp + qq * 512);
      }
    }

    float part = 0.f;
#pragma unroll
    for (int qq = 0; qq < 4; qq++) {
      const unsigned hw[4] = {cur[qq].x, cur[qq].y, cur[qq].z, cur[qq].w};
#pragma unroll
      for (int w = 0; w < 4; w++) {
        const float2 f = h2f2(hw[w]);
        const int b0 = qq * 8 + w * 2;
        part = fmaf(f.x, v_s[tid * 33 + b0],     part);
        part = fmaf(f.y, v_s[tid * 33 + b0 + 1], part);
      }
    }
    part += __shfl_down_sync(0xffffffffu, part, 8, 16);
    part += __shfl_down_sync(0xffffffffu, part, 4, 16);
    part += __shfl_down_sync(0xffffffffu, part, 2, 16);
    part += __shfl_down_sync(0xffffffffu, part, 1, 16);

    float wt = 0.f;
    if (k == 0) {
      const float a = part * (1.f / 32.f);
      const float bnew = (MODE == 1) ? a : (g_bij[c * 32 + u] + a);
      if (MODE == 1) g_bij[c * 32 + u] = bnew;
      wt = __expf(bnew);
      accz += wt;
    }
    wt = __shfl_sync(0xffffffffu, wt, 0, 16);

#pragma unroll
    for (int qq = 0; qq < 4; qq++) {
      const unsigned hw[4] = {cur[qq].x, cur[qq].y, cur[qq].z, cur[qq].w};
#pragma unroll
      for (int w = 0; w < 4; w++) {
        const float2 f = h2f2(hw[w]);
        const int b0 = qq * 8 + w * 2;
        acc[b0]     = fmaf(wt, f.x, acc[b0]);
        acc[b0 + 1] = fmaf(wt, f.y, acc[b0 + 1]);
      }
    }

#pragma unroll
    for (int qq = 0; qq < 4; qq++) cur[qq] = nxt[qq];
  }

#pragma unroll
  for (int b = 0; b < 32; b++)
    g_spart[(size_t)stripe * ELEMS + b * 512 + tg] = acc[b];
  if (k == 0) g_zpart[stripe * 32 + u] = accz;
}

// ---------------- parallel partial reduction (4 threads / element) --------
template <bool WITH_Z>
__global__ void reduce_kernel() {
  __shared__ float red[512];
  __shared__ float zs[256];
  const int tid = threadIdx.x;
  const int sub = tid >> 7;            // 0..3, 38 partials each (4*38=152)
  const int el = tid & 127;
  const int elem = blockIdx.x * 128 + el;

  float s = 0.f;
  const int p0 = sub * 38;
#pragma unroll 4
  for (int i = 0; i < 38; i++)
    s += g_spart[(size_t)(p0 + i) * ELEMS + elem];
  red[tid] = s;
  __syncthreads();
  if (sub == 0)
    g_sred[elem] = red[el] + red[128 + el] + red[256 + el] + red[384 + el];

  if (WITH_Z && blockIdx.x == 0) {
    if (tid < 256) {
      const int u = tid & 31, g = tid >> 5;   // 8 groups x 19 = 152
      float z = 0.f;
#pragma unroll 4
      for (int i = 0; i < 19; i++) z += g_zpart[(g * 19 + i) * 32 + u];
      zs[tid] = z;
    }
    __syncthreads();
    if (tid < 32) {
      float z = 0.f;
#pragma unroll
      for (int g = 0; g < 8; g++) z += zs[g * 32 + tid];
      g_zred[tid] = z;
    }
  }
}

// ---------------- squash --------------------------------------------------
template <int ZMODE, bool FINAL>
__global__ void squash_kernel(float* __restrict__ out) {
  const int gw = blockIdx.x * (blockDim.x >> 5) + (threadIdx.x >> 5);
  const int lane = threadIdx.x & 31;   // = u
  if (gw >= 512) return;
  const int b = gw >> 4, k = gw & 15;
  const int idx = (b * 32 + lane) * 16 + k;

  float s = g_sred[idx];
  const float Z = (ZMODE == 1) ? 8192.f : g_zred[lane];
  s /= Z;

  float msq = s * s;
#pragma unroll
  for (int o = 16; o > 0; o >>= 1) msq += __shfl_xor_sync(0xffffffffu, msq, o);

  const float v = (msq / (1.f + msq)) * s * rsqrtf(msq);
  if (FINAL) out[idx] = v;
  else       g_v[idx] = v;
}

extern "C" void kernel_launch(void* const* d_in, const int* in_sizes, int n_in,
                              void* d_out, int out_size) {
  const float* x = (const float*)d_in[0];   // (32,16,8192)
  const float* W = (const float*)d_in[1];   // (8192,32,16,16)
  if (n_in >= 2 && in_sizes[0] > in_sizes[1]) {
    const float* tmp = x; x = W; W = tmp;
  }
  float* out = (float*)d_out;

  const int SM_P1 = XS_BYTES + 16 * 512 * 8;   // 18688 + 65536 = 84224
  const int SM_V = 256 * 33 * 4;               // 33792
  cudaFuncSetAttribute(pass1_kernel, cudaFuncAttributeMaxDynamicSharedMemorySize, SM_P1);
  cudaFuncSetAttribute(pass23_kernel<1>, cudaFuncAttributeMaxDynamicSharedMemorySize, SM_V);
  cudaFuncSetAttribute(pass23_kernel<2>, cudaFuncAttributeMaxDynamicSharedMemorySize, SM_V);

  // iter 1
  pass1_kernel<<<NSTRIPE, 512, SM_P1>>>(x, W);
  reduce_kernel<false><<<128, 512>>>();
  squash_kernel<1, false><<<16, 1024>>>(nullptr);
  // iter 2
  pass23_kernel<1><<<2 * NSTRIPE, 256, SM_V>>>();
  reduce_kernel<true><<<128, 512>>>();
  squash_kernel<2, false><<<16, 1024>>>(nullptr);
  // iter 3
  pass23_kernel<2><<<2 * NSTRIPE, 256, SM_V>>>();
  reduce_kernel<true><<<128, 512>>>();
  squash_kernel<2, true><<<16, 1024>>>(out);
}

// round 7
// speedup vs baseline: 2.5499x; 1.0678x over previous
#include <cuda_runtime.h>
#include <cuda_fp16.h>
#include <cstddef>

// Digits_Caps dynamic routing. B=32, C=8192, U=32, K=16, I=16, 3 iters.
// pass1: fp32 GEMM u_hat (2t x 16b per thread), register s~, fp16 store coalesced
// pass23: stream fp16 u_hat (2 CTAs/SM), routing update, weighted s~
// reduce: parallel partial reduction; squash: tiny normalize+squash

#define NSTRIPE 152
#define ELEMS 16384   // B*U*K
typedef unsigned long long ull;

// fp16 u_hat: [c][qq=0..3][t=0..511][8 halfs b=8qq..8qq+7] = 256 MB
static __device__ uint4 g_uhat[(size_t)8192 * 4 * 512];
static __device__ float g_spart[NSTRIPE * ELEMS];
static __device__ float g_zpart[NSTRIPE * 32];
static __device__ float g_sred[ELEMS];
static __device__ float g_zred[32];
static __device__ float g_v[ELEMS];
static __device__ float g_bij[8192 * 32];

__device__ __forceinline__ void ffma2(ull& d, const ull a, const ull b) {
  asm("fma.rn.f32x2 %0, %1, %2, %0;" : "+l"(d) : "l"(a), "l"(b));
}
__device__ __forceinline__ void add2(ull& d, const ull a) {
  asm("add.rn.f32x2 %0, %0, %1;" : "+l"(d) : "l"(a));
}
__device__ __forceinline__ ull dup2(float a) {
  unsigned u = __float_as_uint(a);
  return ((ull)u << 32) | u;
}
__device__ __forceinline__ float lo2(ull a) { return __uint_as_float((unsigned)a); }
__device__ __forceinline__ float hi2(ull a) { return __uint_as_float((unsigned)(a >> 32)); }
__device__ __forceinline__ unsigned f2h2(ull a) {   // {lo->low, hi->high}
  unsigned r;
  asm("cvt.rn.f16x2.f32 %0, %1, %2;" : "=r"(r)
      : "r"((unsigned)(a >> 32)), "r"((unsigned)a));
  return r;
}
__device__ __forceinline__ float2 h2f2(unsigned v) {
  __half2 h = *reinterpret_cast<__half2*>(&v);
  return __half22float2(h);
}
__device__ __forceinline__ void pref_l2(const void* p) {
  asm volatile("prefetch.global.L2 [%0];" :: "l"(p));
}

// x_s layout: [j][i][b], i-stride 36 floats (16B aligned), j-stride 584 (bank-spread)
#define XS_J 584
#define XS_I 36
#define XS_BYTES (8 * XS_J * 4)   // 18688

// ---------------- pass 1: GEMM + fp16 u_hat store + register s~ -----------
__global__ __launch_bounds__(512, 1) void pass1_kernel(
    const float* __restrict__ x, const float* __restrict__ W) {
  extern __shared__ char smem_raw[];
  float* x_s = (float*)smem_raw;

  const int t = threadIdx.x;
  const int tl = t & 255;          // base t (also covers t+256)
  const int bh = t >> 8;           // batch half: b in [bh*16, bh*16+16)
  const int bid = blockIdx.x;

  ull acc2[16];                    // s~ partials (packed pairs), register-resident
#pragma unroll
  for (int p = 0; p < 16; p++) acc2[p] = 0ull;

  for (int chunk = bid; chunk < 1024; chunk += NSTRIPE) {
    __syncthreads();
    const int cbase = chunk * 8;
#pragma unroll
    for (int r = 0; r < 8; r++) {
      const int e = t + r * 512;
      const int j = e & 7, bi = e >> 3;
      const int i = bi & 15, b = bi >> 4;
      x_s[j * XS_J + i * XS_I + b] = x[(size_t)bi * 8192 + cbase + j];
    }
    __syncthreads();

#pragma unroll 1
    for (int j = 0; j < 8; j++) {
      const int c = cbase + j;

      // W for the thread's two t values (16 floats each)
      float cwa[16], cwb[16];
      {
        const float4* wa = (const float4*)(W + ((size_t)c * 512 + tl) * 16);
        const float4* wb = (const float4*)(W + ((size_t)c * 512 + tl + 256) * 16);
#pragma unroll
        for (int q = 0; q < 4; q++) {
          float4 va = wa[q], vb = wb[q];
          cwa[4*q]=va.x; cwa[4*q+1]=va.y; cwa[4*q+2]=va.z; cwa[4*q+3]=va.w;
          cwb[4*q]=vb.x; cwb[4*q+1]=vb.y; cwb[4*q+2]=vb.z; cwb[4*q+3]=vb.w;
        }
      }
      // register-free prefetch of next channel's W into L2
      {
        const int cn = (j < 7) ? (c + 1) : (chunk + NSTRIPE) * 8;
        if (cn < 8192) {
          pref_l2(W + ((size_t)cn * 512 + tl) * 16);
          pref_l2(W + ((size_t)cn * 512 + tl + 256) * 16);
        }
      }

      ull uh2[16];   // [tp*8 + bp]: pair b = bh*16 + 2*bp (+1)
#pragma unroll
      for (int p = 0; p < 16; p++) uh2[p] = 0ull;

#pragma unroll
      for (int i = 0; i < 16; i++) {
        const ull wA = dup2(cwa[i]);
        const ull wB = dup2(cwb[i]);
        const ulonglong2* xp =
            (const ulonglong2*)(x_s + j * XS_J + i * XS_I + bh * 16);
#pragma unroll
        for (int q = 0; q < 4; q++) {
          const ulonglong2 xv = xp[q];   // broadcast LDS.128 feeds 4 FFMA2
          ffma2(uh2[2*q],       wA, xv.x);
          ffma2(uh2[2*q + 1],   wA, xv.y);
          ffma2(uh2[8 + 2*q],   wB, xv.x);
          ffma2(uh2[8 + 2*q+1], wB, xv.y);
        }
      }

      // fp16 store, fully coalesced: [c][qq][t]{8 halfs}, qq = 2*bh + qh
#pragma unroll
      for (int tp = 0; tp < 2; tp++) {
#pragma unroll
        for (int qh = 0; qh < 2; qh++) {
          uint4 o;
          o.x = f2h2(uh2[tp*8 + qh*4 + 0]);
          o.y = f2h2(uh2[tp*8 + qh*4 + 1]);
          o.z = f2h2(uh2[tp*8 + qh*4 + 2]);
          o.w = f2h2(uh2[tp*8 + qh*4 + 3]);
          g_uhat[(size_t)c * 2048 + (2*bh + qh) * 512 + tl + tp * 256] = o;
        }
      }
      // s~ accumulate in registers (FMA pipe, 16 add2 per channel)
#pragma unroll
      for (int p = 0; p < 16; p++) add2(acc2[p], uh2[p]);
    }
  }

#pragma unroll
  for (int p = 0; p < 16; p++) {
    const ull v = acc2[p];
    const int b0 = bh * 16 + 2 * (p & 7);
    const int tg = tl + (p >> 3) * 256;
    g_spart[(size_t)bid * ELEMS + b0 * 512 + tg]       = lo2(v);
    g_spart[(size_t)bid * ELEMS + (b0 + 1) * 512 + tg] = hi2(v);
  }
}

// ---------------- passes 2/3: stream fp16 u_hat, routing update -----------
// MODE 1: b_old == 0, write b_ij.  MODE 2: read b_ij (final).
template <int MODE>
__global__ __launch_bounds__(256, 2) void pass23_kernel() {
  extern __shared__ float v_s[];   // [tid][b] stride 33
  const int tid = threadIdx.x;
  const int half = blockIdx.x & 1;
  const int stripe = blockIdx.x >> 1;
  const int tg = half * 256 + tid;
  const int u = tg >> 4;
  const int k = tg & 15;

#pragma unroll
  for (int b = 0; b < 32; b++) v_s[tid * 33 + b] = g_v[b * 512 + tg];
  __syncthreads();

  float acc[32];
#pragma unroll
  for (int b = 0; b < 32; b++) acc[b] = 0.f;
  float accz = 0.f;

  uint4 cur[4];
  {
    const uint4* up = g_uhat + (size_t)stripe * 2048 + tg;
#pragma unroll
    for (int qq = 0; qq < 4; qq++) cur[qq] = up[qq * 512];
  }

#pragma unroll 1
  for (int c = stripe; c < 8192; c += NSTRIPE) {
    const int cn = c + NSTRIPE;
    uint4 nxt[4];
    if (cn < 8192) {
      const uint4* up = g_uhat + (size_t)cn * 2048 + tg;
#pragma unroll
      for (int qq = 0; qq < 4; qq++) nxt[qq] = up[qq * 512];
      if (cn + NSTRIPE < 8192) {
        const uint4* pp = g_uhat + (size_t)(cn + NSTRIPE) * 2048 + tg;
#pragma unroll
        for (int qq = 0; qq < 4; qq++) pref_l2(pp + qq * 512);
      }
    }

    float part = 0.f;
#pragma unroll
    for (int qq = 0; qq < 4; qq++) {
      const unsigned hw[4] = {cur[qq].x, cur[qq].y, cur[qq].z, cur[qq].w};
#pragma unroll
      for (int w = 0; w < 4; w++) {
        const float2 f = h2f2(hw[w]);
        const int b0 = qq * 8 + w * 2;
        part = fmaf(f.x, v_s[tid * 33 + b0],     part);
        part = fmaf(f.y, v_s[tid * 33 + b0 + 1], part);
      }
    }
    part += __shfl_down_sync(0xffffffffu, part, 8, 16);
    part += __shfl_down_sync(0xffffffffu, part, 4, 16);
    part += __shfl_down_sync(0xffffffffu, part, 2, 16);
    part += __shfl_down_sync(0xffffffffu, part, 1, 16);

    float wt = 0.f;
    if (k == 0) {
      const float a = part * (1.f / 32.f);
      const float bnew = (MODE == 1) ? a : (g_bij[c * 32 + u] + a);
      if (MODE == 1) g_bij[c * 32 + u] = bnew;
      wt = __expf(bnew);
      accz += wt;
    }
    wt = __shfl_sync(0xffffffffu, wt, 0, 16);

#pragma unroll
    for (int qq = 0; qq < 4; qq++) {
      const unsigned hw[4] = {cur[qq].x, cur[qq].y, cur[qq].z, cur[qq].w};
#pragma unroll
      for (int w = 0; w < 4; w++) {
        const float2 f = h2f2(hw[w]);
        const int b0 = qq * 8 + w * 2;
        acc[b0]     = fmaf(wt, f.x, acc[b0]);
        acc[b0 + 1] = fmaf(wt, f.y, acc[b0 + 1]);
      }
    }

#pragma unroll
    for (int qq = 0; qq < 4; qq++) cur[qq] = nxt[qq];
  }

#pragma unroll
  for (int b = 0; b < 32; b++)
    g_spart[(size_t)stripe * ELEMS + b * 512 + tg] = acc[b];
  if (k == 0) g_zpart[stripe * 32 + u] = accz;
}

// ---------------- parallel partial reduction (4 threads / element) --------
template <bool WITH_Z>
__global__ void reduce_kernel() {
  __shared__ float red[512];
  __shared__ float zs[256];
  const int tid = threadIdx.x;
  const int sub = tid >> 7;            // 0..3, 38 partials each (4*38=152)
  const int el = tid & 127;
  const int elem = blockIdx.x * 128 + el;

  float s = 0.f;
  const int p0 = sub * 38;
#pragma unroll 4
  for (int i = 0; i < 38; i++)
    s += g_spart[(size_t)(p0 + i) * ELEMS + elem];
  red[tid] = s;
  __syncthreads();
  if (sub == 0)
    g_sred[elem] = red[el] + red[128 + el] + red[256 + el] + red[384 + el];

  if (WITH_Z && blockIdx.x == 0) {
    if (tid < 256) {
      const int u = tid & 31, g = tid >> 5;   // 8 groups x 19 = 152
      float z = 0.f;
#pragma unroll 4
      for (int i = 0; i < 19; i++) z += g_zpart[(g * 19 + i) * 32 + u];
      zs[tid] = z;
    }
    __syncthreads();
    if (tid < 32) {
      float z = 0.f;
#pragma unroll
      for (int g = 0; g < 8; g++) z += zs[g * 32 + tid];
      g_zred[tid] = z;
    }
  }
}

// ---------------- squash --------------------------------------------------
template <int ZMODE, bool FINAL>
__global__ void squash_kernel(float* __restrict__ out) {
  const int gw = blockIdx.x * (blockDim.x >> 5) + (threadIdx.x >> 5);
  const int lane = threadIdx.x & 31;   // = u
  if (gw >= 512) return;
  const int b = gw >> 4, k = gw & 15;
  const int idx = (b * 32 + lane) * 16 + k;

  float s = g_sred[idx];
  const float Z = (ZMODE == 1) ? 8192.f : g_zred[lane];
  s /= Z;

  float msq = s * s;
#pragma unroll
  for (int o = 16; o > 0; o >>= 1) msq += __shfl_xor_sync(0xffffffffu, msq, o);

  const float v = (msq / (1.f + msq)) * s * rsqrtf(msq);
  if (FINAL) out[idx] = v;
  else       g_v[idx] = v;
}

extern "C" void kernel_launch(void* const* d_in, const int* in_sizes, int n_in,
                              void* d_out, int out_size) {
  const float* x = (const float*)d_in[0];   // (32,16,8192)
  const float* W = (const float*)d_in[1];   // (8192,32,16,16)
  if (n_in >= 2 && in_sizes[0] > in_sizes[1]) {
    const float* tmp = x; x = W; W = tmp;
  }
  float* out = (float*)d_out;

  const int SM_P1 = XS_BYTES;      // x tile only (18688 B)
  const int SM_V = 256 * 33 * 4;   // 33792 B
  cudaFuncSetAttribute(pass1_kernel, cudaFuncAttributeMaxDynamicSharedMemorySize, SM_P1);
  cudaFuncSetAttribute(pass23_kernel<1>, cudaFuncAttributeMaxDynamicSharedMemorySize, SM_V);
  cudaFuncSetAttribute(pass23_kernel<2>, cudaFuncAttributeMaxDynamicSharedMemorySize, SM_V);

  // iter 1
  pass1_kernel<<<NSTRIPE, 512, SM_P1>>>(x, W);
  reduce_kernel<false><<<128, 512>>>();
  squash_kernel<1, false><<<16, 1024>>>(nullptr);
  // iter 2
  pass23_kernel<1><<<2 * NSTRIPE, 256, SM_V>>>();
  reduce_kernel<true><<<128, 512>>>();
  squash_kernel<2, false><<<16, 1024>>>(nullptr);
  // iter 3
  pass23_kernel<2><<<2 * NSTRIPE, 256, SM_V>>>();
  reduce_kernel<true><<<128, 512>>>();
  squash_kernel<2, true><<<16, 1024>>>(out);
}